// round 11
// baseline (speedup 1.0000x reference)
#include <cuda_runtime.h>

typedef unsigned long long u64;

#define B  32
#define P  16384
#define O  16
#define NC 80
#define TOTAL4   (B * P * (NC / 4))   // 10,485,760 float4 of conf
#define NSTREAM  1184                 // stream blocks: 148 SMs x 8
#define NMATCH   2048                 // match blocks: (P/256) x B
#define NTOT     (NSTREAM + NMATCH)   // 3232 = 32 x 101; NMATCH/NTOT = 64/101
#define NADJ     128                  // adjust blocks (block 0 = patch)

// ---------------- device scratch (no allocations allowed) ----------------
__device__ float g_overlap[B * P];    // best IoU per prior (pre-override)
__device__ int   g_bidx[B * P];       // best truth per prior (pre-override)
__device__ int   g_poslist[B * P];    // priors with ov >= 0.5
__device__ int   g_invlist[B * P];    // priors with 0.4 <= ov < 0.5
__device__ int   g_npos;
__device__ int   g_ninv;
__device__ u64   g_bestprior[B * O];
__device__ float g_sum_ll;            // loc loss sum
__device__ float g_sum_lcraw;         // sum of g0fast over ALL streamed rows
__device__ float g_sum_corr;          // target-class corrections (true units)
__device__ int   g_posextra;          // forced-pos count added by patch
__device__ int   g_ticket;            // k_adjust completion ticket

// ---------------- math helpers ----------------
__device__ __forceinline__ float frcp(float a) {
    float r; asm("rcp.approx.f32 %0, %1;" : "=f"(r) : "f"(a)); return r;
}

// A&S 4.1.43: ln(1+s) = s*(A1+s*(A2+s*(A3+s*(A4+s*A5)))), |err|<=1e-5 on [0,1]
#define LA1 0.99949556f
#define LA2 (-0.49190896f)
#define LA3 0.28947478f
#define LA4 (-0.13606275f)
#define LA5 0.03215845f

// fast g0(x) = softplus(x)*sigmoid(x): 2 MUFU (ex2, rcp), no divide, no log
__device__ __forceinline__ float g0fast_acc(float x, float acc) {
    float s = __expf(-fabsf(x));                     // exp(-|x|) in (0,1]
    float r = frcp(1.0f + s);
    float q = ((x >= 0.f) ? s : 1.0f) * r;           // sigmoid(-x)
    float L = s * fmaf(s, fmaf(s, fmaf(s, fmaf(s, LA5, LA4), LA3), LA2), LA1);
    float h = fmaxf(x, 0.f) + L;                     // softplus(x)
    return fmaf(h, -q, acc + h);                     // acc + h*(1-q)
}

// full row sum of g0fast (80 classes) for prior bp
__device__ __forceinline__ float row_g0sum(const float4* __restrict__ conf4, int bp) {
    const float4* row = conf4 + (long)bp * 20;
    float s0 = 0.f, s1 = 0.f;
    #pragma unroll
    for (int k = 0; k < 20; k++) {
        float4 v = __ldg(&row[k]);
        s0 = g0fast_acc(v.x, s0);
        s1 = g0fast_acc(v.y, s1);
        s0 = g0fast_acc(v.z, s0);
        s1 = g0fast_acc(v.w, s1);
    }
    return s0 + s1;
}

__device__ __forceinline__ float g0raw(float x) {    // precise (cold paths)
    float e = __expf(-fabsf(x));
    float L = __logf(1.0f + e);
    float h = fmaxf(x, 0.0f) + L;
    float q = __expf(-h);
    return fmaf(-h, q, h);
}

__device__ __forceinline__ float bl1(float diff) {
    const float bb = 19.085537f;                     // e^3 - 1
    float d = fabsf(diff);
    if (d < 0.11f) {
        return (0.5f / bb) * (bb * d + 1.f) * __logf(fmaf(bb * (1.0f / 0.11f), d, 1.0f))
               - 0.5f * d;
    }
    return 1.5f * d + (1.5f / bb - 0.5f * 0.11f);
}

// loc loss + focal target-class correction for a positive prior (b, truth j, prior p)
__device__ __forceinline__ void pos_meta(int b, int j, int p, int bp,
                                         const float4* __restrict__ priors,
                                         const float*  __restrict__ targets,
                                         const float*  __restrict__ conf,
                                         const float4* __restrict__ loc4,
                                         float& ll, float& corr) {
    const float* t = targets + (b * O + j) * 5;
    float m0 = t[0], m1 = t[1], m2 = t[2], m3 = t[3];
    int tc = (int)t[4] + 1;                          // 1..80
    float4 pp = priors[p];
    float rz = frcp(pp.z), rw = frcp(pp.w);
    float ex = ((m0 + m2) * 0.5f - pp.x) * (10.0f * rz);
    float ey = ((m1 + m3) * 0.5f - pp.y) * (10.0f * rw);
    float ew = __logf((m2 - m0) * rz) * 5.0f;        // /0.2
    float eh = __logf((m3 - m1) * rw) * 5.0f;
    float4 ld = loc4[bp];
    ll = bl1(ld.x - ex) + bl1(ld.y - ey) + bl1(ld.z - ew) + bl1(ld.w - eh);
    float x = conf[bp * NC + (tc - 1)];
    corr = 0.25f * g0raw(-x) - 0.75f * g0raw(x);     // focal(x,1) - focal(x,0)
}

// ---------------- fused kernel: heterogeneous blocks (match | stream) ----------
// grid = NTOT. Per 101 consecutive blocks: 64 match, 37 stream (interleaved so
// every SM co-hosts both roles; match ALU fills stream's DRAM stall slots).
__global__ void __launch_bounds__(256, 8) k_main(const float4* __restrict__ priors,
                                                 const float*  __restrict__ targets,
                                                 const float4* __restrict__ conf4) {
    int g   = blockIdx.x;
    int tid = threadIdx.x;
    int mi  = (int)(((unsigned)g * 64u) / 101u);
    int mi2 = (int)(((unsigned)(g + 1) * 64u) / 101u);

    if (mi2 > mi) {
        // ================= MATCH block: priors [256*bx,..) of batch by ==========
        __shared__ float4 s_tr[O];
        __shared__ float  s_area[O];
        __shared__ u64    s_wkey[8][O];

        int bx = mi & 63;
        int b  = mi >> 6;
        int p  = bx * 256 + tid;
        int wid = tid >> 5;

        if (tid < O) {
            const float* t = targets + (b * O + tid) * 5;
            float4 tr = make_float4(t[0], t[1], t[2], t[3]);   // point-form already
            s_tr[tid]   = tr;
            s_area[tid] = (tr.z - tr.x) * (tr.w - tr.y);
        }
        __syncthreads();

        float4 pr = priors[p];
        float px0 = pr.x - pr.z * 0.5f;
        float py0 = pr.y - pr.w * 0.5f;
        float px1 = pr.x + pr.z * 0.5f;
        float py1 = pr.y + pr.w * 0.5f;
        float areaB = (px1 - px0) * (py1 - py0);

        unsigned warpbase = (unsigned)(bx * 256 + (tid & ~31));

        float best = -1.f;
        int   bidx = 0;
        #pragma unroll
        for (int j = 0; j < O; j++) {
            float4 tr = s_tr[j];
            float ix = fmaxf(fminf(tr.z, px1) - fmaxf(tr.x, px0), 0.f);
            float iy = fmaxf(fminf(tr.w, py1) - fmaxf(tr.y, py0), 0.f);
            float inter = ix * iy;
            float iou   = __fdividef(inter, s_area[j] + areaB - inter);
            if (iou > best) { best = iou; bidx = j; }      // first-max (JAX argmax)

            // warp argmax: iou in [0,1] -> float bits order == uint order
            unsigned bits = __float_as_uint(iou);
            unsigned mb   = __reduce_max_sync(0xFFFFFFFFu, bits);
            unsigned bal  = __ballot_sync(0xFFFFFFFFu, bits == mb);
            unsigned pw   = warpbase + (unsigned)(__ffs(bal) - 1);  // smallest p
            s_wkey[wid][j] = ((u64)mb << 32) | (0xFFFFFFFFu - pw);
        }

        int bp = b * P + p;
        g_overlap[bp] = best;
        g_bidx[bp]    = bidx;

        if (best >= 0.5f) {
            int idx = atomicAdd(&g_npos, 1);
            g_poslist[idx] = bp;
        } else if (best >= 0.4f) {
            int idx = atomicAdd(&g_ninv, 1);
            g_invlist[idx] = bp;
        }

        __syncthreads();
        if (tid < O) {
            u64 k = s_wkey[0][tid];
            #pragma unroll
            for (int w = 1; w < 8; w++) k = (s_wkey[w][tid] > k) ? s_wkey[w][tid] : k;
            if (k > g_bestprior[b * O + tid]) atomicMax(&g_bestprior[b * O + tid], k);
        }
    } else {
        // ================= STREAM block: branch-free focal over all conf ========
        int sb = g - mi;                           // stream index in [0, NSTREAM)
        const int stride = NSTREAM * 256;
        float a0 = 0.f, a1 = 0.f;
        #pragma unroll 4
        for (int i = sb * 256 + tid; i < TOTAL4; i += stride) {
            float4 v = __ldcs(&conf4[i]);
            a0 = g0fast_acc(v.x, a0);
            a1 = g0fast_acc(v.y, a1);
            a0 = g0fast_acc(v.z, a0);
            a1 = g0fast_acc(v.w, a1);
        }
        float lc = a0 + a1;
        #pragma unroll
        for (int o = 16; o; o >>= 1) lc += __shfl_down_sync(0xFFFFFFFFu, lc, o);
        __shared__ float s_a[8];
        int wid = tid >> 5, lane = tid & 31;
        if (lane == 0) s_a[wid] = lc;
        __syncthreads();
        if (wid == 0) {
            lc = (lane < 8) ? s_a[lane] : 0.f;
            #pragma unroll
            for (int o = 4; o; o >>= 1) lc += __shfl_down_sync(0xFFFFFFFFu, lc, o);
            if (lane == 0) atomicAdd(&g_sum_lcraw, lc);
        }
    }
}

// ---------------- k_adjust: pos meta + invalid subtraction + patch + finalize ----
// block 0: force-match patch. blocks 1..NADJ-1: poslist meta + invlist row sums.
__global__ void __launch_bounds__(256) k_adjust(const float4* __restrict__ priors,
                                                const float*  __restrict__ targets,
                                                const float*  __restrict__ conf,
                                                const float4* __restrict__ conf4,
                                                const float4* __restrict__ loc4,
                                                float* __restrict__ out) {
    int tid = threadIdx.x;

    if (blockIdx.x == 0) {
        // ---- force-match patch; 512 items over 256 threads ----
        __shared__ unsigned s_p[B * O];
        for (int e = tid; e < B * O; e += 256) {
            u64 key = g_bestprior[e];
            s_p[e] = 0xFFFFFFFFu - (unsigned)(key & 0xFFFFFFFFull);
            g_bestprior[e] = 0ull;             // reset for next replay
        }
        __syncthreads();

        for (int e = tid; e < B * O; e += 256) {
            int b = e >> 4, j = e & 15;
            unsigned p = s_p[e];
            bool apply = true;                 // XLA scatter: last truth wins
            for (int j2 = j + 1; j2 < O; j2++)
                if (s_p[(b << 4) | j2] == p) { apply = false; break; }
            if (!apply) continue;

            int bp = b * P + (int)p;
            float oldov    = g_overlap[bp];
            int   oldj     = g_bidx[bp];
            bool  oldpos   = oldov >= 0.5f;
            bool  oldvalid = oldpos || (oldov < 0.4f);

            float ll_n, corr_n;
            pos_meta(b, j, (int)p, bp, priors, targets, conf, loc4, ll_n, corr_n);
            float dll = ll_n, dcorr = corr_n;
            if (oldpos) {                      // replace old pos contribution exactly
                float ll_o, corr_o;
                pos_meta(b, oldj, (int)p, bp, priors, targets, conf, loc4, ll_o, corr_o);
                dll -= ll_o; dcorr -= corr_o;
            } else {
                atomicAdd(&g_posextra, 1);
            }
            if (!oldvalid)                     // row was subtracted via invlist; add back
                atomicAdd(&g_sum_lcraw, row_g0sum(conf4, bp));
            atomicAdd(&g_sum_ll, dll);
            atomicAdd(&g_sum_corr, dcorr);
        }
        __syncthreads();
    } else {
        // ---- poslist: loc loss + corrections; invlist: subtract rows ----
        int npos = g_npos;
        int ninv = g_ninv;
        const int gstride = (NADJ - 1) * 256;
        float ll = 0.f, corr = 0.f, sub = 0.f;
        for (int e = (blockIdx.x - 1) * 256 + tid; e < npos; e += gstride) {
            int bp = g_poslist[e];
            int b  = bp >> 14;                 // P = 16384
            int p  = bp & (P - 1);
            int j  = g_bidx[bp];
            float l1, c1;
            pos_meta(b, j, p, bp, priors, targets, conf, loc4, l1, c1);
            ll += l1; corr += c1;
        }
        for (int e = (blockIdx.x - 1) * 256 + tid; e < ninv; e += gstride) {
            sub -= row_g0sum(conf4, g_invlist[e]);
        }

        #pragma unroll
        for (int o = 16; o; o >>= 1) {
            ll   += __shfl_down_sync(0xFFFFFFFFu, ll, o);
            corr += __shfl_down_sync(0xFFFFFFFFu, corr, o);
            sub  += __shfl_down_sync(0xFFFFFFFFu, sub, o);
        }
        __shared__ float s_l[8], s_c[8], s_s[8];
        int wid = tid >> 5, lane = tid & 31;
        if (lane == 0) { s_l[wid] = ll; s_c[wid] = corr; s_s[wid] = sub; }
        __syncthreads();
        if (wid == 0) {
            ll   = (lane < 8) ? s_l[lane] : 0.f;
            corr = (lane < 8) ? s_c[lane] : 0.f;
            sub  = (lane < 8) ? s_s[lane] : 0.f;
            #pragma unroll
            for (int o = 4; o; o >>= 1) {
                ll   += __shfl_down_sync(0xFFFFFFFFu, ll, o);
                corr += __shfl_down_sync(0xFFFFFFFFu, corr, o);
                sub  += __shfl_down_sync(0xFFFFFFFFu, sub, o);
            }
            if (lane == 0) {
                if (ll  != 0.f) atomicAdd(&g_sum_ll, ll);
                if (corr!= 0.f) atomicAdd(&g_sum_corr, corr);
                if (sub != 0.f) atomicAdd(&g_sum_lcraw, sub);
            }
        }
        __syncthreads();
    }

    // ---- ticket: last of NADJ blocks finalizes + resets ----
    if (tid == 0) {
        __threadfence();
        if (atomicAdd(&g_ticket, 1) == NADJ - 1) {
            __threadfence();
            float pn = fmaxf((float)(g_npos + g_posextra), 1.0f);
            out[0] = g_sum_ll * frcp(pn * 4.0f);
            out[1] = (0.75f * g_sum_lcraw + g_sum_corr) * frcp(pn);
            g_sum_ll = 0.f; g_sum_lcraw = 0.f; g_sum_corr = 0.f;
            g_npos = 0; g_ninv = 0; g_posextra = 0; g_ticket = 0;
        }
    }
}

// ---------------- launch ----------------
extern "C" void kernel_launch(void* const* d_in, const int* in_sizes, int n_in,
                              void* d_out, int out_size) {
    const float4* loc4    = (const float4*)d_in[0];   // (B,P,4)  f32
    const float4* conf4   = (const float4*)d_in[1];   // (B,P,80) f32
    const float*  conf    = (const float*)d_in[1];
    const float4* priors4 = (const float4*)d_in[2];   // (P,4)    f32
    const float*  targets = (const float*)d_in[3];    // (B,O,5)  f32
    float* out = (float*)d_out;

    k_main<<<NTOT, 256>>>(priors4, targets, conf4);
    k_adjust<<<NADJ, 256>>>(priors4, targets, conf, conf4, loc4, out);
}

// round 12
// speedup vs baseline: 1.7333x; 1.7333x over previous
#include <cuda_runtime.h>

typedef unsigned long long u64;

#define B  32
#define P  16384
#define O  16
#define NC 80
#define TOTAL4   (B * P * (NC / 4))   // 10,485,760 float4 of conf
#define CHUNK4   5120                 // float4 per stolen chunk (80 KB)
#define NCHUNK   (TOTAL4 / CHUNK4)    // 2048 chunks
#define NSTREAM  1184                 // stream-role blocks (work-stealing)
#define NMATCH   2048                 // match blocks: (P/256) x B
#define NTOT     (NSTREAM + NMATCH)   // 3232 = 32 x 101; NMATCH/NTOT = 64/101
#define NADJ     64                   // adjust blocks (block 0 = patch)

// ---------------- device scratch (no allocations allowed) ----------------
__device__ float g_overlap[B * P];    // best IoU per prior (pre-override)
__device__ int   g_bidx[B * P];       // best truth per prior (pre-override)
__device__ int   g_poslist[B * P];    // priors with ov >= 0.5
__device__ int   g_invlist[B * P];    // priors with 0.4 <= ov < 0.5
__device__ int   g_npos;
__device__ int   g_ninv;
__device__ int   g_chunk;             // stream work-stealing cursor
__device__ u64   g_bestprior[B * O];
__device__ float g_sum_ll;            // loc loss sum
__device__ float g_sum_lcraw;         // sum of g0fast over ALL streamed rows
__device__ float g_sum_corr;          // target-class corrections (true units)
__device__ int   g_posextra;          // forced-pos count added by patch
__device__ int   g_ticket;            // k_adjust completion ticket

// ---------------- math helpers ----------------
__device__ __forceinline__ float frcp(float a) {
    float r; asm("rcp.approx.f32 %0, %1;" : "=f"(r) : "f"(a)); return r;
}

// A&S 4.1.43: ln(1+s) = s*(A1+s*(A2+s*(A3+s*(A4+s*A5)))), |err|<=1e-5 on [0,1]
#define LA1 0.99949556f
#define LA2 (-0.49190896f)
#define LA3 0.28947478f
#define LA4 (-0.13606275f)
#define LA5 0.03215845f

// fast g0(x) = softplus(x)*sigmoid(x): 2 MUFU (ex2, rcp), no divide, no log
__device__ __forceinline__ float g0fast_acc(float x, float acc) {
    float s = __expf(-fabsf(x));                     // exp(-|x|) in (0,1]
    float r = frcp(1.0f + s);
    float q = ((x >= 0.f) ? s : 1.0f) * r;           // sigmoid(-x)
    float L = s * fmaf(s, fmaf(s, fmaf(s, fmaf(s, LA5, LA4), LA3), LA2), LA1);
    float h = fmaxf(x, 0.f) + L;                     // softplus(x)
    return fmaf(h, -q, acc + h);                     // acc + h*(1-q)
}

// full row sum of g0fast (80 classes) for prior bp
__device__ __forceinline__ float row_g0sum(const float4* __restrict__ conf4, int bp) {
    const float4* row = conf4 + (long)bp * 20;
    float s0 = 0.f, s1 = 0.f;
    #pragma unroll
    for (int k = 0; k < 20; k++) {
        float4 v = __ldg(&row[k]);
        s0 = g0fast_acc(v.x, s0);
        s1 = g0fast_acc(v.y, s1);
        s0 = g0fast_acc(v.z, s0);
        s1 = g0fast_acc(v.w, s1);
    }
    return s0 + s1;
}

__device__ __forceinline__ float g0raw(float x) {    // precise (cold paths)
    float e = __expf(-fabsf(x));
    float L = __logf(1.0f + e);
    float h = fmaxf(x, 0.0f) + L;
    float q = __expf(-h);
    return fmaf(-h, q, h);
}

__device__ __forceinline__ float bl1(float diff) {
    const float bb = 19.085537f;                     // e^3 - 1
    float d = fabsf(diff);
    if (d < 0.11f) {
        return (0.5f / bb) * (bb * d + 1.f) * __logf(fmaf(bb * (1.0f / 0.11f), d, 1.0f))
               - 0.5f * d;
    }
    return 1.5f * d + (1.5f / bb - 0.5f * 0.11f);
}

// loc loss + focal target-class correction for a positive prior (b, truth j, prior p)
__device__ __forceinline__ void pos_meta(int b, int j, int p, int bp,
                                         const float4* __restrict__ priors,
                                         const float*  __restrict__ targets,
                                         const float*  __restrict__ conf,
                                         const float4* __restrict__ loc4,
                                         float& ll, float& corr) {
    const float* t = targets + (b * O + j) * 5;
    float m0 = t[0], m1 = t[1], m2 = t[2], m3 = t[3];
    int tc = (int)t[4] + 1;                          // 1..80
    float4 pp = priors[p];
    float rz = frcp(pp.z), rw = frcp(pp.w);
    float ex = ((m0 + m2) * 0.5f - pp.x) * (10.0f * rz);
    float ey = ((m1 + m3) * 0.5f - pp.y) * (10.0f * rw);
    float ew = __logf((m2 - m0) * rz) * 5.0f;        // /0.2
    float eh = __logf((m3 - m1) * rw) * 5.0f;
    float4 ld = loc4[bp];
    ll = bl1(ld.x - ex) + bl1(ld.y - ey) + bl1(ld.z - ew) + bl1(ld.w - eh);
    float x = conf[bp * NC + (tc - 1)];
    corr = 0.25f * g0raw(-x) - 0.75f * g0raw(x);     // focal(x,1) - focal(x,0)
}

// ---------------- fused kernel: heterogeneous blocks (match | stream-steal) ----
// Per 101 consecutive blocks: 64 match, 37 stream. Stream blocks steal chunks
// from g_chunk so early-resident blocks absorb the work — no late-start tail.
__global__ void __launch_bounds__(256) k_main(const float4* __restrict__ priors,
                                              const float*  __restrict__ targets,
                                              const float4* __restrict__ conf4) {
    int g   = blockIdx.x;
    int tid = threadIdx.x;
    int mi  = (int)(((unsigned)g * 64u) / 101u);
    int mi2 = (int)(((unsigned)(g + 1) * 64u) / 101u);

    if (mi2 > mi) {
        // ================= MATCH block: priors [256*bx,..) of batch b ==========
        __shared__ float4 s_tr[O];
        __shared__ float  s_area[O];
        __shared__ u64    s_wkey[8][O];

        int bx = mi & 63;
        int b  = mi >> 6;
        int p  = bx * 256 + tid;
        int wid = tid >> 5;

        if (tid < O) {
            const float* t = targets + (b * O + tid) * 5;
            float4 tr = make_float4(t[0], t[1], t[2], t[3]);   // point-form already
            s_tr[tid]   = tr;
            s_area[tid] = (tr.z - tr.x) * (tr.w - tr.y);
        }
        __syncthreads();

        float4 pr = priors[p];
        float px0 = pr.x - pr.z * 0.5f;
        float py0 = pr.y - pr.w * 0.5f;
        float px1 = pr.x + pr.z * 0.5f;
        float py1 = pr.y + pr.w * 0.5f;
        float areaB = (px1 - px0) * (py1 - py0);

        unsigned warpbase = (unsigned)(bx * 256 + (tid & ~31));

        float best = -1.f;
        int   bidx = 0;
        #pragma unroll
        for (int j = 0; j < O; j++) {
            float4 tr = s_tr[j];
            float ix = fmaxf(fminf(tr.z, px1) - fmaxf(tr.x, px0), 0.f);
            float iy = fmaxf(fminf(tr.w, py1) - fmaxf(tr.y, py0), 0.f);
            float inter = ix * iy;
            float iou   = __fdividef(inter, s_area[j] + areaB - inter);
            if (iou > best) { best = iou; bidx = j; }      // first-max (JAX argmax)

            // warp argmax: iou in [0,1] -> float bits order == uint order
            unsigned bits = __float_as_uint(iou);
            unsigned mb   = __reduce_max_sync(0xFFFFFFFFu, bits);
            unsigned bal  = __ballot_sync(0xFFFFFFFFu, bits == mb);
            unsigned pw   = warpbase + (unsigned)(__ffs(bal) - 1);  // smallest p
            s_wkey[wid][j] = ((u64)mb << 32) | (0xFFFFFFFFu - pw);
        }

        int bp = b * P + p;
        g_overlap[bp] = best;
        g_bidx[bp]    = bidx;

        if (best >= 0.5f) {
            int idx = atomicAdd(&g_npos, 1);
            g_poslist[idx] = bp;
        } else if (best >= 0.4f) {
            int idx = atomicAdd(&g_ninv, 1);
            g_invlist[idx] = bp;
        }

        __syncthreads();
        if (tid < O) {
            u64 k = s_wkey[0][tid];
            #pragma unroll
            for (int w = 1; w < 8; w++) k = (s_wkey[w][tid] > k) ? s_wkey[w][tid] : k;
            if (k > g_bestprior[b * O + tid]) atomicMax(&g_bestprior[b * O + tid], k);
        }
    } else {
        // ================= STREAM block: work-stealing focal ====================
        __shared__ int s_c;
        float a0 = 0.f, a1 = 0.f;
        for (;;) {
            if (tid == 0) s_c = atomicAdd(&g_chunk, 1);
            __syncthreads();
            int c = s_c;
            __syncthreads();
            if (c >= NCHUNK) break;
            int base = c * CHUNK4 + tid;
            #pragma unroll 4
            for (int k = 0; k < CHUNK4 / 256; k++) {          // 20 iterations
                float4 v = __ldcs(&conf4[base + k * 256]);
                a0 = g0fast_acc(v.x, a0);
                a1 = g0fast_acc(v.y, a1);
                a0 = g0fast_acc(v.z, a0);
                a1 = g0fast_acc(v.w, a1);
            }
        }
        float lc = a0 + a1;
        #pragma unroll
        for (int o = 16; o; o >>= 1) lc += __shfl_down_sync(0xFFFFFFFFu, lc, o);
        __shared__ float s_a[8];
        int wid = tid >> 5, lane = tid & 31;
        if (lane == 0) s_a[wid] = lc;
        __syncthreads();
        if (wid == 0) {
            lc = (lane < 8) ? s_a[lane] : 0.f;
            #pragma unroll
            for (int o = 4; o; o >>= 1) lc += __shfl_down_sync(0xFFFFFFFFu, lc, o);
            if (lane == 0 && lc != 0.f) atomicAdd(&g_sum_lcraw, lc);
        }
    }
}

// ---------------- k_adjust: pos meta + invalid subtraction + patch + finalize ----
// block 0: force-match patch. blocks 1..NADJ-1: poslist meta + invlist row sums.
__global__ void __launch_bounds__(512) k_adjust(const float4* __restrict__ priors,
                                                const float*  __restrict__ targets,
                                                const float*  __restrict__ conf,
                                                const float4* __restrict__ conf4,
                                                const float4* __restrict__ loc4,
                                                float* __restrict__ out) {
    int tid = threadIdx.x;

    if (blockIdx.x == 0) {
        // ---- force-match patch (tid = b*16 + j); delta-only ----
        __shared__ unsigned s_p[B * O];
        int b = tid >> 4, j = tid & 15;
        u64 key = g_bestprior[tid];
        unsigned p = 0xFFFFFFFFu - (unsigned)(key & 0xFFFFFFFFull);
        s_p[tid] = p;
        g_bestprior[tid] = 0ull;               // reset for next replay
        __syncthreads();

        bool apply = (tid < B * O);            // XLA scatter: last truth wins
        for (int j2 = j + 1; j2 < O && apply; j2++)
            if (s_p[(b << 4) | j2] == p) apply = false;

        if (apply) {
            int bp = b * P + (int)p;
            float oldov    = g_overlap[bp];
            int   oldj     = g_bidx[bp];
            bool  oldpos   = oldov >= 0.5f;
            bool  oldvalid = oldpos || (oldov < 0.4f);

            float ll_n, corr_n;
            pos_meta(b, j, (int)p, bp, priors, targets, conf, loc4, ll_n, corr_n);
            float dll = ll_n, dcorr = corr_n;
            if (oldpos) {                      // replace old pos contribution exactly
                float ll_o, corr_o;
                pos_meta(b, oldj, (int)p, bp, priors, targets, conf, loc4, ll_o, corr_o);
                dll -= ll_o; dcorr -= corr_o;
            } else {
                atomicAdd(&g_posextra, 1);
            }
            if (!oldvalid)                     // row was subtracted via invlist; add back
                atomicAdd(&g_sum_lcraw, row_g0sum(conf4, bp));
            atomicAdd(&g_sum_ll, dll);
            atomicAdd(&g_sum_corr, dcorr);
        }
    } else {
        // ---- poslist: loc loss + corrections; invlist: subtract rows ----
        int npos = g_npos;
        int ninv = g_ninv;
        const int gstride = (NADJ - 1) * 512;
        float ll = 0.f, corr = 0.f, sub = 0.f;
        for (int e = (blockIdx.x - 1) * 512 + tid; e < npos; e += gstride) {
            int bp = g_poslist[e];
            int b  = bp >> 14;                 // P = 16384
            int p  = bp & (P - 1);
            int j  = g_bidx[bp];
            float l1, c1;
            pos_meta(b, j, p, bp, priors, targets, conf, loc4, l1, c1);
            ll += l1; corr += c1;
        }
        for (int e = (blockIdx.x - 1) * 512 + tid; e < ninv; e += gstride) {
            sub -= row_g0sum(conf4, g_invlist[e]);
        }

        #pragma unroll
        for (int o = 16; o; o >>= 1) {
            ll   += __shfl_down_sync(0xFFFFFFFFu, ll, o);
            corr += __shfl_down_sync(0xFFFFFFFFu, corr, o);
            sub  += __shfl_down_sync(0xFFFFFFFFu, sub, o);
        }
        __shared__ float s_l[16], s_c[16], s_s[16];
        int wid = tid >> 5, lane = tid & 31;
        if (lane == 0) { s_l[wid] = ll; s_c[wid] = corr; s_s[wid] = sub; }
        __syncthreads();
        if (wid == 0) {
            ll   = (lane < 16) ? s_l[lane] : 0.f;
            corr = (lane < 16) ? s_c[lane] : 0.f;
            sub  = (lane < 16) ? s_s[lane] : 0.f;
            #pragma unroll
            for (int o = 8; o; o >>= 1) {
                ll   += __shfl_down_sync(0xFFFFFFFFu, ll, o);
                corr += __shfl_down_sync(0xFFFFFFFFu, corr, o);
                sub  += __shfl_down_sync(0xFFFFFFFFu, sub, o);
            }
            if (lane == 0) {
                if (ll  != 0.f) atomicAdd(&g_sum_ll, ll);
                if (corr!= 0.f) atomicAdd(&g_sum_corr, corr);
                if (sub != 0.f) atomicAdd(&g_sum_lcraw, sub);
            }
        }
        __syncthreads();
    }

    // ---- ticket: last of NADJ blocks finalizes + resets ----
    if (tid == 0) {
        __threadfence();
        if (atomicAdd(&g_ticket, 1) == NADJ - 1) {
            __threadfence();
            float pn = fmaxf((float)(g_npos + g_posextra), 1.0f);
            out[0] = g_sum_ll * frcp(pn * 4.0f);
            out[1] = (0.75f * g_sum_lcraw + g_sum_corr) * frcp(pn);
            g_sum_ll = 0.f; g_sum_lcraw = 0.f; g_sum_corr = 0.f;
            g_npos = 0; g_ninv = 0; g_posextra = 0; g_ticket = 0;
            g_chunk = 0;
        }
    }
}

// ---------------- launch ----------------
extern "C" void kernel_launch(void* const* d_in, const int* in_sizes, int n_in,
                              void* d_out, int out_size) {
    const float4* loc4    = (const float4*)d_in[0];   // (B,P,4)  f32
    const float4* conf4   = (const float4*)d_in[1];   // (B,P,80) f32
    const float*  conf    = (const float*)d_in[1];
    const float4* priors4 = (const float4*)d_in[2];   // (P,4)    f32
    const float*  targets = (const float*)d_in[3];    // (B,O,5)  f32
    float* out = (float*)d_out;

    k_main<<<NTOT, 256>>>(priors4, targets, conf4);
    k_adjust<<<NADJ, 512>>>(priors4, targets, conf, conf4, loc4, out);
}